// round 10
// baseline (speedup 1.0000x reference)
#include <cuda_runtime.h>
#include <cuda_fp16.h>

#define NROWS   16384
#define INC     512
#define NG      64
#define NF      24
#define NO      16
#define ACCC    3584
#define RT      32
#define NTHR    256
#define SMEM_BYTES (ACCC * RT * 2)   // 229376 bytes (fp16 tile)

typedef unsigned long long u64;

static __device__ __forceinline__ u64 pk2(float a, float b) {
    u64 r;
    asm("mov.b64 %0, {%1, %2};" : "=l"(r) : "f"(a), "f"(b));
    return r;
}
static __device__ __forceinline__ void up2(u64 v, float &a, float &b) {
    asm("mov.b64 {%0, %1}, %2;" : "=f"(a), "=f"(b) : "l"(v));
}
static __device__ __forceinline__ u64 fma2(u64 a, u64 b, u64 c) {
    u64 d;
    asm("fma.rn.f32x2 %0, %1, %2, %3;" : "=l"(d) : "l"(a), "l"(b), "l"(c));
    return d;
}
static __device__ __forceinline__ float tanhhw(float x) {
    float y;
    asm("tanh.approx.f32 %0, %1;" : "=f"(y) : "f"(x));
    return y;
}
static __device__ __forceinline__ float2 h2f(unsigned u) {
    __half2 h = reinterpret_cast<__half2&>(u);
    return __half22float2(h);
}

// fp16 tile [col][32 rows]: column = 64 B = 4 quads of 16 B (8 rows each).
// Quad s of column c lives at physical quad-slot s ^ H2(c).
// H2 mixes col bits 2..5: spreads banks for random gathers (c arbitrary),
// staging stores (c consecutive), and writeback (c differs by 16 across warp).
#define H2(c)  ((((c) >> 2) ^ ((c) >> 4)) & 3)

static __device__ __forceinline__ uint4* qptr(uint4* tile, int c, int s) {
    return tile + c * 4 + (s ^ H2(c));
}

// Thread = (g, s): group g, row-octet s (rows 8s..8s+7), all 16 outputs.
// Two o-half passes; acc[r][j] = f32x2 over outputs (8h+2j, 8h+2j+1) for
// local row r (0..7). Depth-2 rolling weight prefetch (3 buffers).
static __device__ __forceinline__ void glayer(uint4* tile, int g, int s,
                                              const float* __restrict__ W,
                                              const float* __restrict__ bia,
                                              const int* __restrict__ idx,
                                              int colbase)
{
    int cols[NF];
    const int4* ip = reinterpret_cast<const int4*>(idx + g * NF);
    #pragma unroll
    for (int i = 0; i < NF / 4; i++) {
        int4 v = __ldg(&ip[i]);
        cols[4 * i + 0] = v.x; cols[4 * i + 1] = v.y;
        cols[4 * i + 2] = v.z; cols[4 * i + 3] = v.w;
    }
    const ulonglong2* wb = reinterpret_cast<const ulonglong2*>(W + (size_t)g * NF * NO);
    const float2*     b2 = reinterpret_cast<const float2*>(bia + g * NO);

    #pragma unroll
    for (int h = 0; h < 2; h++) {
        u64 acc[8][4];
        #pragma unroll
        for (int j = 0; j < 4; j++) {
            float2 bb = __ldg(&b2[4 * h + j]);
            u64 bv = pk2(bb.x, bb.y);
            #pragma unroll
            for (int r = 0; r < 8; r++) acc[r][j] = bv;
        }

        // depth-2 rolling prefetch: buffers indexed f%3 (const-folded by unroll)
        ulonglong2 wA[3], wB[3];
        wA[0] = __ldg(&wb[0 * 4 + 2 * h]); wB[0] = __ldg(&wb[0 * 4 + 2 * h + 1]);
        wA[1] = __ldg(&wb[1 * 4 + 2 * h]); wB[1] = __ldg(&wb[1 * 4 + 2 * h + 1]);

        #pragma unroll
        for (int f = 0; f < NF; f++) {
            if (f + 2 < NF) {
                wA[(f + 2) % 3] = __ldg(&wb[(f + 2) * 4 + 2 * h]);
                wB[(f + 2) % 3] = __ldg(&wb[(f + 2) * 4 + 2 * h + 1]);
            }
            int c = cols[f];
            uint4 a = *qptr(tile, c, s);
            float2 r01 = h2f(a.x), r23 = h2f(a.y), r45 = h2f(a.z), r67 = h2f(a.w);
            u64 d0 = pk2(r01.x, r01.x), d1 = pk2(r01.y, r01.y);
            u64 d2 = pk2(r23.x, r23.x), d3 = pk2(r23.y, r23.y);
            u64 d4 = pk2(r45.x, r45.x), d5 = pk2(r45.y, r45.y);
            u64 d6 = pk2(r67.x, r67.x), d7 = pk2(r67.y, r67.y);
            u64 u0 = wA[f % 3].x, u1 = wA[f % 3].y;
            u64 u2 = wB[f % 3].x, u3 = wB[f % 3].y;
            acc[0][0] = fma2(d0, u0, acc[0][0]); acc[0][1] = fma2(d0, u1, acc[0][1]);
            acc[0][2] = fma2(d0, u2, acc[0][2]); acc[0][3] = fma2(d0, u3, acc[0][3]);
            acc[1][0] = fma2(d1, u0, acc[1][0]); acc[1][1] = fma2(d1, u1, acc[1][1]);
            acc[1][2] = fma2(d1, u2, acc[1][2]); acc[1][3] = fma2(d1, u3, acc[1][3]);
            acc[2][0] = fma2(d2, u0, acc[2][0]); acc[2][1] = fma2(d2, u1, acc[2][1]);
            acc[2][2] = fma2(d2, u2, acc[2][2]); acc[2][3] = fma2(d2, u3, acc[2][3]);
            acc[3][0] = fma2(d3, u0, acc[3][0]); acc[3][1] = fma2(d3, u1, acc[3][1]);
            acc[3][2] = fma2(d3, u2, acc[3][2]); acc[3][3] = fma2(d3, u3, acc[3][3]);
            acc[4][0] = fma2(d4, u0, acc[4][0]); acc[4][1] = fma2(d4, u1, acc[4][1]);
            acc[4][2] = fma2(d4, u2, acc[4][2]); acc[4][3] = fma2(d4, u3, acc[4][3]);
            acc[5][0] = fma2(d5, u0, acc[5][0]); acc[5][1] = fma2(d5, u1, acc[5][1]);
            acc[5][2] = fma2(d5, u2, acc[5][2]); acc[5][3] = fma2(d5, u3, acc[5][3]);
            acc[6][0] = fma2(d6, u0, acc[6][0]); acc[6][1] = fma2(d6, u1, acc[6][1]);
            acc[6][2] = fma2(d6, u2, acc[6][2]); acc[6][3] = fma2(d6, u3, acc[6][3]);
            acc[7][0] = fma2(d7, u0, acc[7][0]); acc[7][1] = fma2(d7, u1, acc[7][1]);
            acc[7][2] = fma2(d7, u2, acc[7][2]); acc[7][3] = fma2(d7, u3, acc[7][3]);
        }

        // tanh + fp16 writeback for this o-half: 8 cols x 8 rows
        float v[8][8];   // [row][o-within-half]
        #pragma unroll
        for (int r = 0; r < 8; r++)
            #pragma unroll
            for (int j = 0; j < 4; j++)
                up2(acc[r][j], v[r][2 * j], v[r][2 * j + 1]);
        #pragma unroll
        for (int r = 0; r < 8; r++)
            #pragma unroll
            for (int o = 0; o < 8; o++)
                v[r][o] = tanhhw(v[r][o]);
        #pragma unroll
        for (int o = 0; o < 8; o++) {
            int c = colbase + g * NO + 8 * h + o;
            __half2 p0 = __floats2half2_rn(v[0][o], v[1][o]);
            __half2 p1 = __floats2half2_rn(v[2][o], v[3][o]);
            __half2 p2 = __floats2half2_rn(v[4][o], v[5][o]);
            __half2 p3 = __floats2half2_rn(v[6][o], v[7][o]);
            uint4 st;
            st.x = reinterpret_cast<unsigned&>(p0);
            st.y = reinterpret_cast<unsigned&>(p1);
            st.z = reinterpret_cast<unsigned&>(p2);
            st.w = reinterpret_cast<unsigned&>(p3);
            *qptr(tile, c, s) = st;
        }
    }
}

__global__ void __launch_bounds__(NTHR, 1)
model_kernel(const float* __restrict__ x,
             const float* __restrict__ W1, const float* __restrict__ b1,
             const float* __restrict__ W2, const float* __restrict__ b2,
             const float* __restrict__ W3, const float* __restrict__ b3,
             const float* __restrict__ Wo, const float* __restrict__ bo,
             const int* __restrict__ idx1, const int* __restrict__ idx2,
             const int* __restrict__ idx3, const int* __restrict__ idxo,
             float* __restrict__ out)
{
    extern __shared__ uint4 tile[];  // [ACCC][4 quads] fp16, quad-hash swizzle
    const int t = threadIdx.x;
    const int rowbase = blockIdx.x * RT;

    // ---- Stage x tile (32 rows x 512 cols) fp32->fp16 into SMEM ----
    // item = (quad qd, col c): 8 LDG.32 coalesced over c, one STS.128.
    {
        const float* xb = x + (size_t)rowbase * INC;
        #pragma unroll
        for (int k = 0; k < 8; k++) {
            int i  = t + k * NTHR;       // 0..2047
            int c  = i & 511;
            int qd = i >> 9;             // 0..3
            float r0 = __ldg(&xb[(8 * qd + 0) * INC + c]);
            float r1 = __ldg(&xb[(8 * qd + 1) * INC + c]);
            float r2 = __ldg(&xb[(8 * qd + 2) * INC + c]);
            float r3 = __ldg(&xb[(8 * qd + 3) * INC + c]);
            float r4 = __ldg(&xb[(8 * qd + 4) * INC + c]);
            float r5 = __ldg(&xb[(8 * qd + 5) * INC + c]);
            float r6 = __ldg(&xb[(8 * qd + 6) * INC + c]);
            float r7 = __ldg(&xb[(8 * qd + 7) * INC + c]);
            __half2 p0 = __floats2half2_rn(r0, r1);
            __half2 p1 = __floats2half2_rn(r2, r3);
            __half2 p2 = __floats2half2_rn(r4, r5);
            __half2 p3 = __floats2half2_rn(r6, r7);
            uint4 st;
            st.x = reinterpret_cast<unsigned&>(p0);
            st.y = reinterpret_cast<unsigned&>(p1);
            st.z = reinterpret_cast<unsigned&>(p2);
            st.w = reinterpret_cast<unsigned&>(p3);
            *qptr(tile, c, qd) = st;
        }
    }
    __syncthreads();

    const int g = t >> 2;   // group 0..63
    const int s = t & 3;    // row-octet 0..3

    glayer(tile, g, s, W1, b1, idx1, 512);
    __syncthreads();
    glayer(tile, g, s, W2, b2, idx2, 1536);
    __syncthreads();
    glayer(tile, g, s, W3, b3, idx3, 2560);
    __syncthreads();

    // ---- Output layer: 4 groups x 48 f x 16 o, linear, fp32 out ----
    // thread = (ot, og, so): output col ot of group og, rows 8so..8so+7.
    {
        int ot = t & 15;
        int og = (t >> 4) & 3;
        int so = t >> 6;                 // 0..3
        float bias = __ldg(&bo[og * 16 + ot]);
        u64 bd = pk2(bias, bias);
        u64 hacc[4] = {bd, bd, bd, bd};  // row pairs (0,1) (2,3) (4,5) (6,7)
        const int* gi = idxo + og * 48;
        const float* w = Wo + og * 48 * 16 + ot;
        #pragma unroll
        for (int f = 0; f < 48; f++) {
            int c = __ldg(&gi[f]);
            uint4 a = *qptr(tile, c, so);
            float2 r01 = h2f(a.x), r23 = h2f(a.y), r45 = h2f(a.z), r67 = h2f(a.w);
            float wf = __ldg(&w[f * 16]);
            u64 wd = pk2(wf, wf);
            hacc[0] = fma2(pk2(r01.x, r01.y), wd, hacc[0]);
            hacc[1] = fma2(pk2(r23.x, r23.y), wd, hacc[1]);
            hacc[2] = fma2(pk2(r45.x, r45.y), wd, hacc[2]);
            hacc[3] = fma2(pk2(r67.x, r67.y), wd, hacc[3]);
        }
        float hv[8];
        #pragma unroll
        for (int j = 0; j < 4; j++) up2(hacc[j], hv[2 * j], hv[2 * j + 1]);
        float* ob = out + (size_t)(rowbase + 8 * so) * 64 + og * 16 + ot;
        #pragma unroll
        for (int r = 0; r < 8; r++)
            ob[(size_t)r * 64] = hv[r];
    }
}

extern "C" void kernel_launch(void* const* d_in, const int* in_sizes, int n_in,
                              void* d_out, int out_size)
{
    const float* x   = (const float*)d_in[0];
    const float* W1  = (const float*)d_in[1];
    const float* b1  = (const float*)d_in[2];
    const float* W2  = (const float*)d_in[3];
    const float* b2  = (const float*)d_in[4];
    const float* W3  = (const float*)d_in[5];
    const float* b3  = (const float*)d_in[6];
    const float* Wo  = (const float*)d_in[7];
    const float* bo  = (const float*)d_in[8];
    const int*   i1  = (const int*)d_in[9];
    const int*   i2  = (const int*)d_in[10];
    const int*   i3  = (const int*)d_in[11];
    const int*   io  = (const int*)d_in[12];
    float*       out = (float*)d_out;

    cudaFuncSetAttribute(model_kernel,
                         cudaFuncAttributeMaxDynamicSharedMemorySize, SMEM_BYTES);
    model_kernel<<<NROWS / RT, NTHR, SMEM_BYTES>>>(
        x, W1, b1, W2, b2, W3, b3, Wo, bo, i1, i2, i3, io, out);
}